// round 17
// baseline (speedup 1.0000x reference)
#include <cuda_runtime.h>
#include <math.h>
#include <stdint.h>

// Gating: x[B=8,S=8192,H=512] f32, gate_w[E=4,H], gate_b[E]
// Outputs concatenated in d_out (float32):
//   [0, 4T)   sparse_logits   [4T,6T) indices(float)   [6T,10T) gate_logit
// T = B*S = 65536.

#define HIDDEN 512
#define NEXP 4
#define NTOK 65536
#define TPW 4                          // tokens per warp
#define WARPS 8                        // 256 threads
#define TILE_TOK (TPW * WARPS)         // 32 tokens per block
#define NBLOCKS (NTOK / TILE_TOK)      // 2048

// dynamic smem layout (bytes):
//   [0, 8192)        gate_w staged (4 x 512 f32)
//   [8192, 8208)     gate_b (4 f32)
//   [8208, 8216)     mbarrier
//   [8320, 73856)    x tile: 32 tokens x 512 f32 = 64KB (128B aligned)
#define SM_W 0
#define SM_B 8192
#define SM_MBAR 8208
#define SM_X 8320
#define SM_TOTAL (SM_X + TILE_TOK * HIDDEN * 4)
#define XTILE_BYTES (TILE_TOK * HIDDEN * 4)   // 65536

__device__ __forceinline__ uint32_t smem_u32(const void* p) {
    uint32_t a;
    asm("{ .reg .u64 t; cvta.to.shared.u64 t, %1; cvt.u32.u64 %0, t; }"
        : "=r"(a) : "l"(p));
    return a;
}

__global__ __launch_bounds__(256) void gating_kernel(
    const float* __restrict__ x,
    const float* __restrict__ gate_w,
    const float* __restrict__ gate_b,
    float* __restrict__ out)
{
    extern __shared__ char smem[];
    float4* sgw4 = (float4*)(smem + SM_W);           // 512 float4
    float*  sgb  = (float*)(smem + SM_B);
    float4* sx   = (float4*)(smem + SM_X);           // 32*128 float4

    int tid    = threadIdx.x;
    int warpid = tid >> 5;
    int lane   = tid & 31;
    int half   = lane >> 4;            // bit4
    int quart  = (lane >> 3) & 1;      // bit3

    uint32_t mbar = smem_u32(smem + SM_MBAR);
    uint32_t xdst = smem_u32(smem + SM_X);

    if (tid == 0) {
        asm volatile("mbarrier.init.shared.b64 [%0], %1;"
                     :: "r"(mbar), "r"(1) : "memory");
    }
    __syncthreads();

    // ---- one bulk async copy: this block's whole x tile (64KB) ----
    if (tid == 0) {
        const char* src = (const char*)(x + (size_t)blockIdx.x * TILE_TOK * HIDDEN);
        asm volatile("mbarrier.arrive.expect_tx.shared.b64 _, [%0], %1;"
                     :: "r"(mbar), "r"((uint32_t)XTILE_BYTES) : "memory");
        asm volatile("cp.async.bulk.shared::cta.global.mbarrier::complete_tx::bytes "
                     "[%0], [%1], %2, [%3];"
                     :: "r"(xdst), "l"(src), "r"((uint32_t)XTILE_BYTES), "r"(mbar)
                     : "memory");
    }

    // stage weights while the bulk copy streams
    for (int i = tid; i < NEXP * (HIDDEN / 4); i += 256) {
        sgw4[i] = ((const float4*)gate_w)[i];
    }
    if (tid < NEXP) sgb[tid] = gate_b[tid];
    __syncthreads();

    // wait for the x tile
    {
        uint32_t done = 0;
        while (!done) {
            asm volatile(
                "{\n\t"
                ".reg .pred p;\n\t"
                "mbarrier.try_wait.parity.shared.b64 p, [%1], %2, 0x989680;\n\t"
                "selp.b32 %0, 1, 0, p;\n\t"
                "}"
                : "=r"(done) : "r"(mbar), "r"(0u) : "memory");
        }
    }

    // ---- compute: TPW=4 tokens per warp, chunk-major, expert-major ----
    int tloc = warpid * TPW;           // this warp's first token within the tile

    float acc[TPW][NEXP];
#pragma unroll
    for (int t = 0; t < TPW; t++)
#pragma unroll
        for (int e = 0; e < NEXP; e++) acc[t][e] = 0.f;

#pragma unroll
    for (int i = 0; i < 4; i++) {
        int h = lane + i * 32;
        float4 v[TPW];
#pragma unroll
        for (int t = 0; t < TPW; t++)
            v[t] = sx[(tloc + t) * (HIDDEN / 4) + h];
#pragma unroll
        for (int e = 0; e < NEXP; e++) {
            float4 w = sgw4[e * (HIDDEN / 4) + h];
#pragma unroll
            for (int t = 0; t < TPW; t++) {
                acc[t][e] += v[t].x * w.x + v[t].y * w.y
                           + v[t].z * w.z + v[t].w * w.w;
            }
        }
    }

    // ---- deep fold reduce (validated R13 scheme) ----
#pragma unroll
    for (int t = 0; t < TPW; t++)
#pragma unroll
        for (int e = 0; e < NEXP; e++)
            acc[t][e] += __shfl_xor_sync(0xFFFFFFFFu, acc[t][e], 16);

    float b[2][NEXP];
#pragma unroll
    for (int j = 0; j < 2; j++)
#pragma unroll
        for (int e = 0; e < NEXP; e++)
            b[j][e] = half ? acc[2 + j][e] : acc[j][e];

#pragma unroll
    for (int j = 0; j < 2; j++)
#pragma unroll
        for (int e = 0; e < NEXP; e++)
            b[j][e] += __shfl_xor_sync(0xFFFFFFFFu, b[j][e], 8);

    float c[NEXP];
#pragma unroll
    for (int e = 0; e < NEXP; e++)
        c[e] = quart ? b[1][e] : b[0][e];

#pragma unroll
    for (int o = 4; o > 0; o >>= 1)
#pragma unroll
        for (int e = 0; e < NEXP; e++)
            c[e] += __shfl_xor_sync(0xFFFFFFFFu, c[e], o);

    // lanes 0,8,16,24 each finish one token
    if ((lane & 7) == 0) {
        int token = blockIdx.x * TILE_TOK + tloc + (lane >> 3);

        float l[NEXP];
#pragma unroll
        for (int e = 0; e < NEXP; e++) l[e] = c[e] + sgb[e];

        // gate_logit (raw logits)
        float4* glog = (float4*)(out + (size_t)6 * NTOK);
        glog[token] = make_float4(l[0], l[1], l[2], l[3]);

        // top-2 (earlier index wins ties, matching jax top_k)
        int i0 = 0; float m0 = l[0];
#pragma unroll
        for (int e = 1; e < NEXP; e++) { if (l[e] > m0) { m0 = l[e]; i0 = e; } }
        int i1 = -1; float m1 = -INFINITY;
#pragma unroll
        for (int e = 0; e < NEXP; e++) {
            if (e != i0 && l[e] > m1) { m1 = l[e]; i1 = e; }
        }

        // softmax over {m0, m1}
        float e1 = __expf(m1 - m0);
        float inv = 1.0f / (1.0f + e1);

        float sp[NEXP] = {0.f, 0.f, 0.f, 0.f};
        sp[i0] = inv;
        sp[i1] = e1 * inv;
        float4* spv = (float4*)out;
        spv[token] = make_float4(sp[0], sp[1], sp[2], sp[3]);

        float2* idx = (float2*)(out + (size_t)4 * NTOK);
        idx[token] = make_float2((float)i0, (float)i1);
    }
}

extern "C" void kernel_launch(void* const* d_in, const int* in_sizes, int n_in,
                              void* d_out, int out_size)
{
    const float* x      = (const float*)d_in[0];
    const float* gate_w = (const float*)d_in[1];
    const float* gate_b = (const float*)d_in[2];
    float* out = (float*)d_out;

    cudaFuncSetAttribute(gating_kernel,
                         cudaFuncAttributeMaxDynamicSharedMemorySize, SM_TOTAL);
    gating_kernel<<<NBLOCKS, 256, SM_TOTAL>>>(x, gate_w, gate_b, out);
}